// round 1
// baseline (speedup 1.0000x reference)
#include <cuda_runtime.h>
#include <math.h>

#define TT    256
#define IN_F  1024
#define HID_F 1024
#define OUT_F 1024
#define BB    128
#define HB    (HID_F * BB)
#define NSPLIT 8

// Scratch (allocation-free rule: __device__ globals)
__device__ float g_A[(size_t)TT * HB];      // Wxh @ x_t + bh, all t  (134 MB)
__device__ float g_H[(size_t)TT * HB];      // h_t for all t          (134 MB)
__device__ float g_P[(size_t)NSPLIT * HB];  // split-K partials (4 MB)

// ---------------------------------------------------------------------------
// C[t] = W(1024 x K) @ X[t](K x 128) + bias   (tile 128x128, BK=8, 8x8/thread)
// X[t] = Xb + t*xstride, C[t] = Cb + t*cstride, both row stride 128.
// ---------------------------------------------------------------------------
__global__ __launch_bounds__(256) void gemm_full(
    const float* __restrict__ W, const float* __restrict__ Xb,
    const float* __restrict__ bias, float* __restrict__ Cb,
    int K, long long xstride, long long cstride)
{
    __shared__ float Ws[8][128];   // transposed: Ws[k][m]
    __shared__ float Xs[8][128];

    const int tid = threadIdx.x;
    const int m0  = blockIdx.x * 128;
    const float* X = Xb + (long long)blockIdx.y * xstride;
    float*       C = Cb + (long long)blockIdx.y * cstride;

    const int tm = (tid >> 4) * 8;
    const int tn = (tid & 15) * 8;

    float acc[8][8];
#pragma unroll
    for (int i = 0; i < 8; i++)
#pragma unroll
        for (int j = 0; j < 8; j++) acc[i][j] = 0.f;

    const int wrow = tid >> 1;          // 0..127
    const int wkq  = (tid & 1) * 4;     // 0 or 4
    const int xrow = tid >> 5;          // 0..7
    const int xcol = (tid & 31) * 4;    // 0..124

    for (int k0 = 0; k0 < K; k0 += 8) {
        float4 w = *(const float4*)(W + (long long)(m0 + wrow) * K + k0 + wkq);
        float4 x = *(const float4*)(X + (long long)(k0 + xrow) * BB + xcol);
        __syncthreads();
        Ws[wkq + 0][wrow] = w.x;
        Ws[wkq + 1][wrow] = w.y;
        Ws[wkq + 2][wrow] = w.z;
        Ws[wkq + 3][wrow] = w.w;
        *(float4*)&Xs[xrow][xcol] = x;
        __syncthreads();
#pragma unroll
        for (int kk = 0; kk < 8; kk++) {
            float a[8], b[8];
            *(float4*)&a[0] = *(const float4*)&Ws[kk][tm];
            *(float4*)&a[4] = *(const float4*)&Ws[kk][tm + 4];
            *(float4*)&b[0] = *(const float4*)&Xs[kk][tn];
            *(float4*)&b[4] = *(const float4*)&Xs[kk][tn + 4];
#pragma unroll
            for (int i = 0; i < 8; i++)
#pragma unroll
                for (int j = 0; j < 8; j++)
                    acc[i][j] += a[i] * b[j];
        }
    }

#pragma unroll
    for (int i = 0; i < 8; i++) {
        const float bv = bias[m0 + tm + i];
        float4 o0 = make_float4(acc[i][0] + bv, acc[i][1] + bv,
                                acc[i][2] + bv, acc[i][3] + bv);
        float4 o1 = make_float4(acc[i][4] + bv, acc[i][5] + bv,
                                acc[i][6] + bv, acc[i][7] + bv);
        float* crow = C + (long long)(m0 + tm + i) * BB + tn;
        *(float4*)(crow)     = o0;
        *(float4*)(crow + 4) = o1;
    }
}

// ---------------------------------------------------------------------------
// Split-K partial for the recurrence: P[s] = Whh[:, s*128:(s+1)*128] @ h_{t-1}[s*128:(s+1)*128, :]
// tile 64x128, K-chunk 128, BK=8, 4x8/thread. grid (16 m-tiles, 8 splits) = 128 CTAs
// ---------------------------------------------------------------------------
__global__ __launch_bounds__(256) void step_partial(
    const float* __restrict__ Whh, const float* __restrict__ h_prev_in, int t)
{
    __shared__ float Ws[8][64];
    __shared__ float Xs[8][128];

    const int tid   = threadIdx.x;
    const int m0    = blockIdx.x * 64;
    const int s     = blockIdx.y;
    const int kbase = s * 128;
    const float* H  = (t == 0) ? h_prev_in : (g_H + (long long)(t - 1) * HB);
    float*       P  = g_P + (long long)s * HB;

    const int tm = (tid >> 4) * 4;
    const int tn = (tid & 15) * 8;
    float acc[4][8];
#pragma unroll
    for (int i = 0; i < 4; i++)
#pragma unroll
        for (int j = 0; j < 8; j++) acc[i][j] = 0.f;

    const int wrow = tid >> 2;        // 0..63
    const int wkq  = (tid & 3) * 2;   // 0,2,4,6
    const int xrow = tid >> 5;
    const int xcol = (tid & 31) * 4;

    for (int k0 = 0; k0 < 128; k0 += 8) {
        float2 w = *(const float2*)(Whh + (long long)(m0 + wrow) * HID_F + kbase + k0 + wkq);
        float4 x = *(const float4*)(H + (long long)(kbase + k0 + xrow) * BB + xcol);
        __syncthreads();
        Ws[wkq + 0][wrow] = w.x;
        Ws[wkq + 1][wrow] = w.y;
        *(float4*)&Xs[xrow][xcol] = x;
        __syncthreads();
#pragma unroll
        for (int kk = 0; kk < 8; kk++) {
            float a[4], b[8];
            *(float4*)&a[0] = *(const float4*)&Ws[kk][tm];
            *(float4*)&b[0] = *(const float4*)&Xs[kk][tn];
            *(float4*)&b[4] = *(const float4*)&Xs[kk][tn + 4];
#pragma unroll
            for (int i = 0; i < 4; i++)
#pragma unroll
                for (int j = 0; j < 8; j++)
                    acc[i][j] += a[i] * b[j];
        }
    }

#pragma unroll
    for (int i = 0; i < 4; i++) {
        float* prow = P + (long long)(m0 + tm + i) * BB + tn;
        *(float4*)(prow)     = make_float4(acc[i][0], acc[i][1], acc[i][2], acc[i][3]);
        *(float4*)(prow + 4) = make_float4(acc[i][4], acc[i][5], acc[i][6], acc[i][7]);
    }
}

// h_t = tanh(A[t] + sum_s P[s])
__global__ __launch_bounds__(256) void step_reduce(int t)
{
    const int idx = blockIdx.x * 256 + threadIdx.x;   // 512 * 256 = 131072 = HB
    float v = g_A[(long long)t * HB + idx];
#pragma unroll
    for (int s = 0; s < NSPLIT; s++) v += g_P[(long long)s * HB + idx];
    g_H[(long long)t * HB + idx] = tanhf(v);
}

__global__ __launch_bounds__(256) void copy_final(float* __restrict__ out)
{
    const int idx = blockIdx.x * 256 + threadIdx.x;   // 512 * 256 = HB
    out[(long long)TT * OUT_F * BB + idx] = g_H[(long long)(TT - 1) * HB + idx];
}

// ---------------------------------------------------------------------------
extern "C" void kernel_launch(void* const* d_in, const int* in_sizes, int n_in,
                              void* d_out, int out_size)
{
    (void)in_sizes; (void)n_in; (void)out_size;
    const float* inputs = (const float*)d_in[0];   // [T, IN, B]
    const float* h_prev = (const float*)d_in[1];   // [HID, B]
    const float* Wxh    = (const float*)d_in[2];   // [HID, IN]
    const float* Whh    = (const float*)d_in[3];   // [HID, HID]
    const float* Why    = (const float*)d_in[4];   // [OUT, HID]
    const float* bh     = (const float*)d_in[5];   // [HID]
    const float* by     = (const float*)d_in[6];   // [OUT]
    float* out = (float*)d_out;                    // ys [T,OUT,B] then h_final [HID,B]

    float *pA = nullptr, *pH = nullptr;
    cudaGetSymbolAddress((void**)&pA, g_A);
    cudaGetSymbolAddress((void**)&pH, g_H);

    // 1) A[t] = Wxh @ x_t + bh, all t in parallel
    gemm_full<<<dim3(8, TT), 256>>>(Wxh, inputs, bh, pA,
                                    IN_F, (long long)IN_F * BB, (long long)HB);

    // 2) serial recurrence: h_t = tanh(A[t] + Whh @ h_{t-1})
    for (int t = 0; t < TT; ++t) {
        step_partial<<<dim3(16, NSPLIT), 256>>>(Whh, h_prev, t);
        step_reduce<<<512, 256>>>(t);
    }

    // 3) y_t = Why @ h_t + by, all t in parallel, straight into d_out
    gemm_full<<<dim3(8, TT), 256>>>(Why, pH, by, out,
                                    HID_F, (long long)HB, (long long)OUT_F * BB);

    // 4) h_final
    copy_final<<<512, 256>>>(out);
}

// round 6
// speedup vs baseline: 1.4235x; 1.4235x over previous
#include <cuda_runtime.h>
#include <math.h>

#define TT    256
#define IN_F  1024
#define HID_F 1024
#define OUT_F 1024
#define BB    128
#define HB    (HID_F * BB)

// Scratch (allocation-free rule: __device__ globals)
// g_S[t] = pre-activation state: Wxh@x_t + bh + Whh@h_{t-1}; h_t = tanh(g_S[t])
__device__ float g_S[(size_t)TT * HB];      // 134 MB

// ---------------------------------------------------------------------------
// C[t] = W(1024 x K) @ f(X[t])(K x 128) + bias  (tile 128x128, BK=8, 8x8/thr)
// TANHX: apply tanhf to X elements on load (X holds pre-activation state).
// ---------------------------------------------------------------------------
template <bool TANHX>
__global__ __launch_bounds__(256) void gemm_full(
    const float* __restrict__ W, const float* __restrict__ Xb,
    const float* __restrict__ bias, float* __restrict__ Cb,
    int K, long long xstride, long long cstride)
{
    __shared__ float Ws[8][128];   // transposed: Ws[k][m]
    __shared__ float Xs[8][128];

    const int tid = threadIdx.x;
    const int m0  = blockIdx.x * 128;
    const float* X = Xb + (long long)blockIdx.y * xstride;
    float*       C = Cb + (long long)blockIdx.y * cstride;

    const int tm = (tid >> 4) * 8;
    const int tn = (tid & 15) * 8;

    float acc[8][8];
#pragma unroll
    for (int i = 0; i < 8; i++)
#pragma unroll
        for (int j = 0; j < 8; j++) acc[i][j] = 0.f;

    const int wrow = tid >> 1;
    const int wkq  = (tid & 1) * 4;
    const int xrow = tid >> 5;
    const int xcol = (tid & 31) * 4;

    for (int k0 = 0; k0 < K; k0 += 8) {
        float4 w = *(const float4*)(W + (long long)(m0 + wrow) * K + k0 + wkq);
        float4 x = *(const float4*)(X + (long long)(k0 + xrow) * BB + xcol);
        if (TANHX) {
            x.x = tanhf(x.x); x.y = tanhf(x.y);
            x.z = tanhf(x.z); x.w = tanhf(x.w);
        }
        __syncthreads();
        Ws[wkq + 0][wrow] = w.x;
        Ws[wkq + 1][wrow] = w.y;
        Ws[wkq + 2][wrow] = w.z;
        Ws[wkq + 3][wrow] = w.w;
        *(float4*)&Xs[xrow][xcol] = x;
        __syncthreads();
#pragma unroll
        for (int kk = 0; kk < 8; kk++) {
            float a[8], b[8];
            *(float4*)&a[0] = *(const float4*)&Ws[kk][tm];
            *(float4*)&a[4] = *(const float4*)&Ws[kk][tm + 4];
            *(float4*)&b[0] = *(const float4*)&Xs[kk][tn];
            *(float4*)&b[4] = *(const float4*)&Xs[kk][tn + 4];
#pragma unroll
            for (int i = 0; i < 8; i++)
#pragma unroll
                for (int j = 0; j < 8; j++)
                    acc[i][j] += a[i] * b[j];
        }
    }

#pragma unroll
    for (int i = 0; i < 8; i++) {
        const float bv = bias[m0 + tm + i];
        float4 o0 = make_float4(acc[i][0] + bv, acc[i][1] + bv,
                                acc[i][2] + bv, acc[i][3] + bv);
        float4 o1 = make_float4(acc[i][4] + bv, acc[i][5] + bv,
                                acc[i][6] + bv, acc[i][7] + bv);
        float* crow = C + (long long)(m0 + tm + i) * BB + tn;
        *(float4*)(crow)     = o0;
        *(float4*)(crow + 4) = o1;
    }
}

// ---------------------------------------------------------------------------
// One recurrence step (launched per t):
//   dst += Whh[:, ks] @ tanh?(src[ks, :])     via atomicAdd (REDG)
// grid (16 m-tiles, 8 k-splits) = 128 CTAs, 256 threads.
// Double-buffered smem pipeline: one __syncthreads per BK=8 chunk.
// src = h_prev (do_tanh=0) for t=0, else g_S[t-1] (do_tanh=1).
// ---------------------------------------------------------------------------
__global__ __launch_bounds__(256) void rnn_step(
    const float* __restrict__ Whh, const float* __restrict__ src,
    float* __restrict__ dst, int do_tanh)
{
    __shared__ float Ws[2][8][64];    // [buf][k][m]  4 KB
    __shared__ float Xs[2][8][128];   // [buf][k][b]  8 KB

    const int tid   = threadIdx.x;
    const int m0    = blockIdx.x * 64;
    const int kbase = blockIdx.y * 128;

    const float* Wp = Whh + (long long)kbase;
    const float* Hs = src + (long long)kbase * BB;

    const int tm = (tid >> 4) * 4;    // 0..60
    const int tn = (tid & 15) * 8;    // 0..120

    const int wrow = tid >> 2;        // 0..63
    const int wkq  = (tid & 3) * 2;   // 0,2,4,6
    const int xrow = tid >> 5;        // 0..7
    const int xcol = (tid & 31) * 4;  // 0..124

    float acc[4][8];
#pragma unroll
    for (int i = 0; i < 4; i++)
#pragma unroll
        for (int j = 0; j < 8; j++) acc[i][j] = 0.f;

    // prefetch chunk 0
    {
        float2 w = *(const float2*)(Wp + (long long)(m0 + wrow) * HID_F + wkq);
        float4 x = *(const float4*)(Hs + (long long)xrow * BB + xcol);
        if (do_tanh) {
            x.x = tanhf(x.x); x.y = tanhf(x.y);
            x.z = tanhf(x.z); x.w = tanhf(x.w);
        }
        Ws[0][wkq + 0][wrow] = w.x;
        Ws[0][wkq + 1][wrow] = w.y;
        *(float4*)&Xs[0][xrow][xcol] = x;
    }
    __syncthreads();

#pragma unroll 2
    for (int c = 0; c < 16; c++) {
        const int buf = c & 1;
        float2 wn; float4 xn;
        if (c < 15) {
            const int kk0 = (c + 1) * 8;
            wn = *(const float2*)(Wp + (long long)(m0 + wrow) * HID_F + kk0 + wkq);
            xn = *(const float4*)(Hs + (long long)(kk0 + xrow) * BB + xcol);
            if (do_tanh) {
                xn.x = tanhf(xn.x); xn.y = tanhf(xn.y);
                xn.z = tanhf(xn.z); xn.w = tanhf(xn.w);
            }
        }
#pragma unroll
        for (int kk = 0; kk < 8; kk++) {
            float a[4], b[8];
            *(float4*)&a[0] = *(const float4*)&Ws[buf][kk][tm];
            *(float4*)&b[0] = *(const float4*)&Xs[buf][kk][tn];
            *(float4*)&b[4] = *(const float4*)&Xs[buf][kk][tn + 4];
#pragma unroll
            for (int i = 0; i < 4; i++)
#pragma unroll
                for (int j = 0; j < 8; j++)
                    acc[i][j] += a[i] * b[j];
        }
        if (c < 15) {
            Ws[buf ^ 1][wkq + 0][wrow] = wn.x;
            Ws[buf ^ 1][wkq + 1][wrow] = wn.y;
            *(float4*)&Xs[buf ^ 1][xrow][xcol] = xn;
        }
        __syncthreads();
    }

    // accumulate partials into dst (REDG, no return value -> no L1 hazard;
    // cross-launch visibility guaranteed by kernel boundary)
#pragma unroll
    for (int i = 0; i < 4; i++) {
        float* pr = dst + (long long)(m0 + tm + i) * BB + tn;
#pragma unroll
        for (int j = 0; j < 8; j++)
            atomicAdd(pr + j, acc[i][j]);
    }
}

// h_final = tanh(S[T-1])
__global__ __launch_bounds__(256) void copy_final(float* __restrict__ out)
{
    const int idx = blockIdx.x * 256 + threadIdx.x;   // 512 * 256 = HB
    out[(long long)TT * OUT_F * BB + idx] =
        tanhf(g_S[(long long)(TT - 1) * HB + idx]);
}

// ---------------------------------------------------------------------------
extern "C" void kernel_launch(void* const* d_in, const int* in_sizes, int n_in,
                              void* d_out, int out_size)
{
    (void)in_sizes; (void)n_in; (void)out_size;
    const float* inputs = (const float*)d_in[0];   // [T, IN, B]
    const float* h_prev = (const float*)d_in[1];   // [HID, B]
    const float* Wxh    = (const float*)d_in[2];   // [HID, IN]
    const float* Whh    = (const float*)d_in[3];   // [HID, HID]
    const float* Why    = (const float*)d_in[4];   // [OUT, HID]
    const float* bh     = (const float*)d_in[5];   // [HID]
    const float* by     = (const float*)d_in[6];   // [OUT]
    float* out = (float*)d_out;                    // ys [T,OUT,B] then h_final

    float* pS = nullptr;
    cudaGetSymbolAddress((void**)&pS, g_S);

    // 1) S[t] = Wxh @ x_t + bh, all t in parallel
    gemm_full<false><<<dim3(8, TT), 256>>>(Wxh, inputs, bh, pS,
                                           IN_F, (long long)IN_F * BB,
                                           (long long)HB);

    // 2) serial recurrence: S[t] += Whh @ tanh?(S[t-1]); one launch per step
    for (int t = 0; t < TT; ++t) {
        const float* src = (t == 0) ? h_prev : (pS + (long long)(t - 1) * HB);
        rnn_step<<<dim3(16, 8), 256>>>(Whh, src, pS + (long long)t * HB,
                                       t == 0 ? 0 : 1);
    }

    // 3) y_t = Why @ tanh(S[t]) + by, all t in parallel, into d_out
    gemm_full<true><<<dim3(8, TT), 256>>>(Why, pS, by, out,
                                          HID_F, (long long)HB,
                                          (long long)OUT_F * BB);

    // 4) h_final
    copy_final<<<512, 256>>>(out);
}